// round 15
// baseline (speedup 1.0000x reference)
#include <cuda_runtime.h>
#include <cstdint>

#define N_NODES 100000
#define N_EDGES 3200000
#define IN_F    128

// ---------------- scratch (no allocations allowed) ----------------
// device globals are zero-initialized at load; every call restores agg/cnt to
// zero before exit, so graph replays see the same initial state.
__device__ float g_yr[N_NODES * 32];    // [n][0:16]=y, [n][16:32]=r ; updated in place each stage
__device__ float g_agg[N_NODES * 16];   // neighbor-sum accumulator (zeroed by fused combine)
__device__ float g_cnt[N_NODES];        // in-degree (zeroed by fused combine #2)

// packed f32x2 FMA (Blackwell; ptxas never emits FFMA2 from C++)
__device__ __forceinline__ void ffma2(unsigned long long& d,
                                      unsigned long long a,
                                      unsigned long long b) {
    asm("fma.rn.f32x2 %0, %1, %2, %0;" : "+l"(d) : "l"(a), "l"(b));
}
__device__ __forceinline__ unsigned long long pack2(float v) {
    unsigned long long r;
    asm("mov.b64 %0, {%1, %1};" : "=l"(r) : "f"(v));
    return r;
}

// PDL: wait for programmatic predecessor's trigger (+mem visibility);
// trigger allows dependents to launch once ALL threads triggered or exited.
__device__ __forceinline__ void pdl_wait() {
    asm volatile("griddepcontrol.wait;" ::: "memory");
}
__device__ __forceinline__ void pdl_trigger() {
    asm volatile("griddepcontrol.launch_dependents;" ::: "memory");
}

// ---------------- kernels ----------------

// y|r = x @ [w1_l | w1_r]   (128 -> 32), weights in shared.
// Weights read as LDS.128 (float4 -> ulonglong2), math as f32x2 packed FMA:
// per k: 8 LDS.128 + 16 FFMA2 (was 16 LDS.64 + 16 FFMA2).
__global__ void k_gemm_in(const float* __restrict__ x,
                          const float* __restrict__ wl,
                          const float* __restrict__ wr) {
    __shared__ float sw[IN_F * 32];
    for (int i = threadIdx.x; i < IN_F * 32; i += blockDim.x) {
        int k = i >> 5, c = i & 31;
        sw[i] = (c < 16) ? wl[k * 16 + c] : wr[k * 16 + (c - 16)];
    }
    __syncthreads();
    int n = blockIdx.x * blockDim.x + threadIdx.x;
    if (n >= N_NODES) { pdl_trigger(); return; }

    unsigned long long acc2[16];
#pragma unroll
    for (int j = 0; j < 16; j++) acc2[j] = 0ull;

    const float4* xr = (const float4*)(x + (size_t)n * IN_F);
    const ulonglong2* sw2 = (const ulonglong2*)sw;   // 16B = 4 floats = 2 f32x2

#pragma unroll 4
    for (int k4 = 0; k4 < IN_F / 4; k4++) {
        float4 xv = __ldg(xr + k4);
        float xs[4] = {xv.x, xv.y, xv.z, xv.w};
#pragma unroll
        for (int i = 0; i < 4; i++) {
            unsigned long long xx = pack2(xs[i]);
            int k = k4 * 4 + i;
#pragma unroll
            for (int j = 0; j < 8; j++) {
                ulonglong2 w = sw2[k * 8 + j];       // uniform smem addr -> broadcast LDS.128
                ffma2(acc2[2 * j + 0], xx, w.x);
                ffma2(acc2[2 * j + 1], xx, w.y);
            }
        }
    }
    ulonglong2* o = (ulonglong2*)(g_yr + (size_t)n * 32);
#pragma unroll
    for (int j = 0; j < 8; j++)
        o[j] = make_ulonglong2(acc2[2 * j], acc2[2 * j + 1]);
    pdl_trigger();
}

// edge scatter: thread-quad handles TWO edges (2 independent gather->red chains
// for MLP); lane c of the quad moves 16B chunk c of each edge's 64B y row.
__global__ void k_scatter(const int* __restrict__ ei, int addCnt) {
    int t = blockIdx.x * blockDim.x + threadIdx.x;
    if (t >= N_EDGES * 2) return;              // exit counts as trigger
    int q = t >> 2, c = t & 3;
    int e0 = 2 * q, e1 = 2 * q + 1;
    int s0 = __ldg(ei + e0);                   // harness input: safe pre-wait
    int d0 = __ldg(ei + N_EDGES + e0);
    int s1 = __ldg(ei + e1);
    int d1 = __ldg(ei + N_EDGES + e1);
    pdl_wait();                                // g_yr / zeroed g_agg ready
    float4 v0 = *(const float4*)(g_yr + (size_t)s0 * 32 + 4 * c);
    float4 v1 = *(const float4*)(g_yr + (size_t)s1 * 32 + 4 * c);
    float* p0 = g_agg + (size_t)d0 * 16 + 4 * c;
    float* p1 = g_agg + (size_t)d1 * 16 + 4 * c;
    asm volatile("red.global.add.v4.f32 [%0], {%1,%2,%3,%4};"
                 :: "l"(p0), "f"(v0.x), "f"(v0.y), "f"(v0.z), "f"(v0.w) : "memory");
    asm volatile("red.global.add.v4.f32 [%0], {%1,%2,%3,%4};"
                 :: "l"(p1), "f"(v1.x), "f"(v1.y), "f"(v1.z), "f"(v1.w) : "memory");
    if (addCnt && c == 0) {
        atomicAdd(g_cnt + d0, 1.0f);
        atomicAdd(g_cnt + d1, 1.0f);
    }
    pdl_trigger();
}

// Fused combine + 16->32 GEMM, thread per node, in-place on g_yr:
//   h_j = relu(agg[n][j]/max(cnt,1) + bc[j] + yr[n][16+j])
//   yr[n][c] = sum_k h_k * sw[k][c] (+bo[c] on c<16)
// Re-zeroes agg row (and cnt if zeroCnt) so the next call starts clean.
// sw[k][c] = (c<16) ? wa[k][c] : wb[k+offB][c-16]
__global__ void k_comb16(const float* __restrict__ wa,
                         const float* __restrict__ wb,
                         const float* __restrict__ bc,
                         const float* __restrict__ bo,
                         int offB, int zeroCnt) {
    __shared__ float sw[16 * 32];
    __shared__ float sbc[16], sbo[16];
    for (int i = threadIdx.x; i < 16 * 32; i += blockDim.x) {
        int k = i >> 5, c = i & 31;
        sw[i] = (c < 16) ? wa[k * 16 + c] : wb[(k + offB) * 16 + (c - 16)];
    }
    if (threadIdx.x < 16) {
        sbc[threadIdx.x] = bc[threadIdx.x];
        sbo[threadIdx.x] = bo ? bo[threadIdx.x] : 0.f;
    }
    __syncthreads();                            // weight staging overlaps predecessor
    int n = blockIdx.x * blockDim.x + threadIdx.x;
    if (n >= N_NODES) { pdl_trigger(); return; }
    pdl_wait();                                 // agg/cnt complete

    // load agg row + residual chunk, compute h in registers
    float4* ag = (float4*)(g_agg + (size_t)n * 16);
    const float4* rr = (const float4*)(g_yr + (size_t)n * 32 + 16);
    float cnt = g_cnt[n];
    float inv = __fdividef(1.f, fmaxf(cnt, 1.f));

    float h[16];
#pragma unroll
    for (int q = 0; q < 4; q++) {
        float4 a = ag[q];
        float4 r = rr[q];
        h[4 * q + 0] = fmaxf(fmaf(a.x, inv, sbc[4 * q + 0] + r.x), 0.f);
        h[4 * q + 1] = fmaxf(fmaf(a.y, inv, sbc[4 * q + 1] + r.y), 0.f);
        h[4 * q + 2] = fmaxf(fmaf(a.z, inv, sbc[4 * q + 2] + r.z), 0.f);
        h[4 * q + 3] = fmaxf(fmaf(a.w, inv, sbc[4 * q + 3] + r.w), 0.f);
    }
    // restore invariant for next stage / replay
    float4 z4 = make_float4(0.f, 0.f, 0.f, 0.f);
#pragma unroll
    for (int q = 0; q < 4; q++) ag[q] = z4;
    if (zeroCnt) g_cnt[n] = 0.f;

    // 16 -> 32 GEMM from shared weights
    float acc[32];
#pragma unroll
    for (int j = 0; j < 32; j++) acc[j] = 0.f;
    const float4* sw4 = (const float4*)sw;
#pragma unroll
    for (int k = 0; k < 16; k++) {
        float xk = h[k];
#pragma unroll
        for (int j = 0; j < 8; j++) {
            float4 w = sw4[k * 8 + j];
            acc[4 * j + 0] = fmaf(xk, w.x, acc[4 * j + 0]);
            acc[4 * j + 1] = fmaf(xk, w.y, acc[4 * j + 1]);
            acc[4 * j + 2] = fmaf(xk, w.z, acc[4 * j + 2]);
            acc[4 * j + 3] = fmaf(xk, w.w, acc[4 * j + 3]);
        }
    }
#pragma unroll
    for (int j = 0; j < 16; j++) acc[j] += sbo[j];

    float4* o = (float4*)(g_yr + (size_t)n * 32);   // in-place: row n read+written by this thread only
#pragma unroll
    for (int j = 0; j < 8; j++)
        o[j] = make_float4(acc[4 * j], acc[4 * j + 1], acc[4 * j + 2], acc[4 * j + 3]);
    pdl_trigger();
}

// per edge, 4 cooperative lanes: z = relu(a[src] + b[dst]) ; o = z @ fc2 + fc2_b ; log_softmax
__global__ void k_edge(const int* __restrict__ ei,
                       const float* __restrict__ fc2w,
                       const float* __restrict__ fc2b,
                       float* __restrict__ out) {
    __shared__ float sf[34];
    if (threadIdx.x < 32) sf[threadIdx.x] = fc2w[threadIdx.x];
    if (threadIdx.x < 2)  sf[32 + threadIdx.x] = fc2b[threadIdx.x];
    __syncthreads();
    int t = blockIdx.x * blockDim.x + threadIdx.x;
    if (t >= N_EDGES * 4) return;
    int e = t >> 2, c = t & 3;
    int s = __ldg(ei + e);
    int d = __ldg(ei + N_EDGES + e);
    pdl_wait();                                  // a|b table complete
    float4 a = *(const float4*)(g_yr + (size_t)s * 32 + 4 * c);       // a chunk
    float4 b = *(const float4*)(g_yr + (size_t)d * 32 + 16 + 4 * c);  // b chunk
    float z0 = fmaxf(a.x + b.x, 0.f);
    float z1 = fmaxf(a.y + b.y, 0.f);
    float z2 = fmaxf(a.z + b.z, 0.f);
    float z3 = fmaxf(a.w + b.w, 0.f);
    int j = 4 * c;
    float o0, o1;
    o0 = z0 * sf[(j + 0) * 2 + 0];                 o1 = z0 * sf[(j + 0) * 2 + 1];
    o0 = fmaf(z1, sf[(j + 1) * 2 + 0], o0);        o1 = fmaf(z1, sf[(j + 1) * 2 + 1], o1);
    o0 = fmaf(z2, sf[(j + 2) * 2 + 0], o0);        o1 = fmaf(z2, sf[(j + 2) * 2 + 1], o1);
    o0 = fmaf(z3, sf[(j + 3) * 2 + 0], o0);        o1 = fmaf(z3, sf[(j + 3) * 2 + 1], o1);
    // reduce over the 4 lanes of this edge
    o0 += __shfl_xor_sync(~0u, o0, 1);  o1 += __shfl_xor_sync(~0u, o1, 1);
    o0 += __shfl_xor_sync(~0u, o0, 2);  o1 += __shfl_xor_sync(~0u, o1, 2);
    if (c == 0) {
        o0 += sf[32]; o1 += sf[33];
        float m = fmaxf(o0, o1);
        float l = m + __logf(__expf(o0 - m) + __expf(o1 - m));
        ((float2*)out)[e] = make_float2(o0 - l, o1 - l);
    }
}

// ---------------- launch ----------------

template <typename... Args>
static void launch_pdl(void (*kern)(Args...), dim3 grid, dim3 block, Args... args) {
    cudaLaunchConfig_t cfg = {};
    cfg.gridDim = grid;
    cfg.blockDim = block;
    cfg.stream = 0;   // same (legacy default) stream as <<<>>> launches
    cudaLaunchAttribute attr[1];
    attr[0].id = cudaLaunchAttributeProgrammaticStreamSerialization;
    attr[0].val.programmaticStreamSerializationAllowed = 1;
    cfg.attrs = attr;
    cfg.numAttrs = 1;
    cudaLaunchKernelEx(&cfg, kern, args...);
}

extern "C" void kernel_launch(void* const* d_in, const int* in_sizes, int n_in,
                              void* d_out, int out_size) {
    const float* x    = (const float*)d_in[0];
    const int*   ei   = (const int*)  d_in[1];
    const float* w1l  = (const float*)d_in[2];
    const float* b1l  = (const float*)d_in[3];
    const float* w1r  = (const float*)d_in[4];
    const float* w2l  = (const float*)d_in[5];
    const float* b2l  = (const float*)d_in[6];
    const float* w2r  = (const float*)d_in[7];
    const float* fc1w = (const float*)d_in[8];
    const float* fc1b = (const float*)d_in[9];
    const float* fc2w = (const float*)d_in[10];
    const float* fc2b = (const float*)d_in[11];
    float* out = (float*)d_out;

    const int TB = 256;
    int gG  = (N_NODES + 127) / 128;          // 782, thread-per-node kernels
    int gE2 = (N_EDGES * 2 + TB - 1) / TB;    // 25000, dual-edge scatter
    int gE4 = (N_EDGES * 4 + TB - 1) / TB;    // 50000, 4-lane edge kernel

    // A = x @ [w1_l|w1_r]  (normal launch: full order vs previous replay's k_edge)
    k_gemm_in<<<gG, 128>>>(x, w1l, w1r);
    // layer 1: scatter y -> agg (+cnt); fused combine+GEMM -> y|r (in place), zero agg
    launch_pdl(k_scatter, dim3(gE2), dim3(TB), ei, 1);
    launch_pdl(k_comb16, dim3(gG), dim3(128), w2l, w2r, b1l, (const float*)nullptr, 0, 0);
    // layer 2: scatter y -> agg; fused combine+GEMM with fc1 -> a|b, zero agg + cnt
    launch_pdl(k_scatter, dim3(gE2), dim3(TB), ei, 0);
    launch_pdl(k_comb16, dim3(gG), dim3(128), fc1w, fc1w, b2l, fc1b, 16, 1);
    // per-edge head + log_softmax (4 lanes per edge)
    launch_pdl(k_edge, dim3(gE4), dim3(TB), ei, fc2w, fc2b, out);
}

// round 16
// speedup vs baseline: 1.1153x; 1.1153x over previous
#include <cuda_runtime.h>
#include <cstdint>

#define N_NODES 100000
#define N_EDGES 3200000
#define IN_F    128

// ---------------- scratch (no allocations allowed) ----------------
// device globals are zero-initialized at load; every call restores agg/cnt to
// zero before exit, so graph replays see the same initial state.
__device__ float g_yr[N_NODES * 32];    // [n][0:16]=y, [n][16:32]=r ; updated in place each stage
__device__ float g_agg[N_NODES * 16];   // neighbor-sum accumulator (zeroed by fused combine)
__device__ float g_cnt[N_NODES];        // in-degree (zeroed by fused combine #2)

// packed f32x2 FMA (Blackwell; ptxas never emits FFMA2 from C++)
__device__ __forceinline__ void ffma2(unsigned long long& d,
                                      unsigned long long a,
                                      unsigned long long b) {
    asm("fma.rn.f32x2 %0, %1, %2, %0;" : "+l"(d) : "l"(a), "l"(b));
}
__device__ __forceinline__ unsigned long long pack2(float v) {
    unsigned long long r;
    asm("mov.b64 %0, {%1, %1};" : "=l"(r) : "f"(v));
    return r;
}

// PDL: wait for programmatic predecessor's trigger (+mem visibility);
// trigger allows dependents to launch once ALL threads triggered or exited.
__device__ __forceinline__ void pdl_wait() {
    asm volatile("griddepcontrol.wait;" ::: "memory");
}
__device__ __forceinline__ void pdl_trigger() {
    asm volatile("griddepcontrol.launch_dependents;" ::: "memory");
}

// ---------------- kernels ----------------

// y|r = x @ [w1_l | w1_r]   (128 -> 32), weights in shared.
// Weights read as LDS.128 (float4 -> ulonglong2), math as f32x2 packed FMA.
__global__ void k_gemm_in(const float* __restrict__ x,
                          const float* __restrict__ wl,
                          const float* __restrict__ wr) {
    __shared__ float sw[IN_F * 32];
    for (int i = threadIdx.x; i < IN_F * 32; i += blockDim.x) {
        int k = i >> 5, c = i & 31;
        sw[i] = (c < 16) ? wl[k * 16 + c] : wr[k * 16 + (c - 16)];
    }
    __syncthreads();
    int n = blockIdx.x * blockDim.x + threadIdx.x;
    if (n >= N_NODES) { pdl_trigger(); return; }

    unsigned long long acc2[16];
#pragma unroll
    for (int j = 0; j < 16; j++) acc2[j] = 0ull;

    const float4* xr = (const float4*)(x + (size_t)n * IN_F);
    const ulonglong2* sw2 = (const ulonglong2*)sw;   // 16B = 4 floats = 2 f32x2

#pragma unroll 4
    for (int k4 = 0; k4 < IN_F / 4; k4++) {
        float4 xv = __ldg(xr + k4);
        float xs[4] = {xv.x, xv.y, xv.z, xv.w};
#pragma unroll
        for (int i = 0; i < 4; i++) {
            unsigned long long xx = pack2(xs[i]);
            int k = k4 * 4 + i;
#pragma unroll
            for (int j = 0; j < 8; j++) {
                ulonglong2 w = sw2[k * 8 + j];       // uniform smem addr -> broadcast LDS.128
                ffma2(acc2[2 * j + 0], xx, w.x);
                ffma2(acc2[2 * j + 1], xx, w.y);
            }
        }
    }
    ulonglong2* o = (ulonglong2*)(g_yr + (size_t)n * 32);
#pragma unroll
    for (int j = 0; j < 8; j++)
        o[j] = make_ulonglong2(acc2[2 * j], acc2[2 * j + 1]);
    pdl_trigger();
}

// edge scatter: thread-quad handles FOUR edges (4 independent gather->red chains
// for MLP); lane c of the quad moves 16B chunk c of each edge's 64B y row.
__global__ void k_scatter(const int* __restrict__ ei, int addCnt) {
    int t = blockIdx.x * blockDim.x + threadIdx.x;
    if (t >= N_EDGES) return;                  // exit counts as trigger
    int base = (t >> 2) * 4, c = t & 3;
    int s[4], d[4];
#pragma unroll
    for (int u = 0; u < 4; u++) {
        s[u] = __ldg(ei + base + u);           // harness input: safe pre-wait
        d[u] = __ldg(ei + N_EDGES + base + u);
    }
    pdl_wait();                                // g_yr / zeroed g_agg ready
    float4 v[4];
#pragma unroll
    for (int u = 0; u < 4; u++)
        v[u] = *(const float4*)(g_yr + (size_t)s[u] * 32 + 4 * c);
#pragma unroll
    for (int u = 0; u < 4; u++) {
        float* p = g_agg + (size_t)d[u] * 16 + 4 * c;
        asm volatile("red.global.add.v4.f32 [%0], {%1,%2,%3,%4};"
                     :: "l"(p), "f"(v[u].x), "f"(v[u].y), "f"(v[u].z), "f"(v[u].w) : "memory");
    }
    if (addCnt && c == 0) {
#pragma unroll
        for (int u = 0; u < 4; u++) atomicAdd(g_cnt + d[u], 1.0f);
    }
    pdl_trigger();
}

// Fused combine + 16->32 GEMM, thread per node, in-place on g_yr:
//   h_j = relu(agg[n][j]/max(cnt,1) + bc[j] + yr[n][16+j])
//   yr[n][c] = sum_k h_k * sw[k][c] (+bo[c] on c<16)
// Re-zeroes agg row (and cnt if zeroCnt) so the next call starts clean.
// sw[k][c] = (c<16) ? wa[k][c] : wb[k+offB][c-16]
__global__ void k_comb16(const float* __restrict__ wa,
                         const float* __restrict__ wb,
                         const float* __restrict__ bc,
                         const float* __restrict__ bo,
                         int offB, int zeroCnt) {
    __shared__ float sw[16 * 32];
    __shared__ float sbc[16], sbo[16];
    for (int i = threadIdx.x; i < 16 * 32; i += blockDim.x) {
        int k = i >> 5, c = i & 31;
        sw[i] = (c < 16) ? wa[k * 16 + c] : wb[(k + offB) * 16 + (c - 16)];
    }
    if (threadIdx.x < 16) {
        sbc[threadIdx.x] = bc[threadIdx.x];
        sbo[threadIdx.x] = bo ? bo[threadIdx.x] : 0.f;
    }
    __syncthreads();                            // weight staging overlaps predecessor
    int n = blockIdx.x * blockDim.x + threadIdx.x;
    if (n >= N_NODES) { pdl_trigger(); return; }
    pdl_wait();                                 // agg/cnt complete

    // load agg row + residual chunk, compute h in registers
    float4* ag = (float4*)(g_agg + (size_t)n * 16);
    const float4* rr = (const float4*)(g_yr + (size_t)n * 32 + 16);
    float cnt = g_cnt[n];
    float inv = __fdividef(1.f, fmaxf(cnt, 1.f));

    float h[16];
#pragma unroll
    for (int q = 0; q < 4; q++) {
        float4 a = ag[q];
        float4 r = rr[q];
        h[4 * q + 0] = fmaxf(fmaf(a.x, inv, sbc[4 * q + 0] + r.x), 0.f);
        h[4 * q + 1] = fmaxf(fmaf(a.y, inv, sbc[4 * q + 1] + r.y), 0.f);
        h[4 * q + 2] = fmaxf(fmaf(a.z, inv, sbc[4 * q + 2] + r.z), 0.f);
        h[4 * q + 3] = fmaxf(fmaf(a.w, inv, sbc[4 * q + 3] + r.w), 0.f);
    }
    // restore invariant for next stage / replay
    float4 z4 = make_float4(0.f, 0.f, 0.f, 0.f);
#pragma unroll
    for (int q = 0; q < 4; q++) ag[q] = z4;
    if (zeroCnt) g_cnt[n] = 0.f;

    // 16 -> 32 GEMM from shared weights
    float acc[32];
#pragma unroll
    for (int j = 0; j < 32; j++) acc[j] = 0.f;
    const float4* sw4 = (const float4*)sw;
#pragma unroll
    for (int k = 0; k < 16; k++) {
        float xk = h[k];
#pragma unroll
        for (int j = 0; j < 8; j++) {
            float4 w = sw4[k * 8 + j];
            acc[4 * j + 0] = fmaf(xk, w.x, acc[4 * j + 0]);
            acc[4 * j + 1] = fmaf(xk, w.y, acc[4 * j + 1]);
            acc[4 * j + 2] = fmaf(xk, w.z, acc[4 * j + 2]);
            acc[4 * j + 3] = fmaf(xk, w.w, acc[4 * j + 3]);
        }
    }
#pragma unroll
    for (int j = 0; j < 16; j++) acc[j] += sbo[j];

    float4* o = (float4*)(g_yr + (size_t)n * 32);   // in-place: row n read+written by this thread only
#pragma unroll
    for (int j = 0; j < 8; j++)
        o[j] = make_float4(acc[4 * j], acc[4 * j + 1], acc[4 * j + 2], acc[4 * j + 3]);
    pdl_trigger();
}

// per edge, 4 cooperative lanes, TWO edges per quad.
// 2-class log-softmax via delta: z = relu(a[s]+b[d]);
// delta = sum_k z_k*(w_k1-w_k0) + (b1-b0); out = (-sp(delta), delta-sp(delta)).
// Lane 0 of the quad writes both edges' outputs as one float4 (16B coalesced).
__global__ void k_edge(const int* __restrict__ ei,
                       const float* __restrict__ fc2w,
                       const float* __restrict__ fc2b,
                       float* __restrict__ out) {
    __shared__ float sdw[16];
    __shared__ float sdb;
    if (threadIdx.x < 16) sdw[threadIdx.x] = fc2w[2 * threadIdx.x + 1] - fc2w[2 * threadIdx.x];
    if (threadIdx.x == 0) sdb = fc2b[1] - fc2b[0];
    __syncthreads();
    int t = blockIdx.x * blockDim.x + threadIdx.x;
    if (t >= N_EDGES * 2) return;
    int q = t >> 2, c = t & 3;
    int e0 = 2 * q, e1 = 2 * q + 1;
    int s0 = __ldg(ei + e0), d0 = __ldg(ei + N_EDGES + e0);
    int s1 = __ldg(ei + e1), d1 = __ldg(ei + N_EDGES + e1);
    pdl_wait();                                  // a|b table complete
    float4 a0 = *(const float4*)(g_yr + (size_t)s0 * 32 + 4 * c);
    float4 b0 = *(const float4*)(g_yr + (size_t)d0 * 32 + 16 + 4 * c);
    float4 a1 = *(const float4*)(g_yr + (size_t)s1 * 32 + 4 * c);
    float4 b1 = *(const float4*)(g_yr + (size_t)d1 * 32 + 16 + 4 * c);
    float w0 = sdw[4 * c + 0], w1 = sdw[4 * c + 1], w2 = sdw[4 * c + 2], w3 = sdw[4 * c + 3];

    float dl0, dl1;
    dl0 =      fmaxf(a0.x + b0.x, 0.f) * w0;
    dl0 = fmaf(fmaxf(a0.y + b0.y, 0.f), w1, dl0);
    dl0 = fmaf(fmaxf(a0.z + b0.z, 0.f), w2, dl0);
    dl0 = fmaf(fmaxf(a0.w + b0.w, 0.f), w3, dl0);
    dl1 =      fmaxf(a1.x + b1.x, 0.f) * w0;
    dl1 = fmaf(fmaxf(a1.y + b1.y, 0.f), w1, dl1);
    dl1 = fmaf(fmaxf(a1.z + b1.z, 0.f), w2, dl1);
    dl1 = fmaf(fmaxf(a1.w + b1.w, 0.f), w3, dl1);
    // reduce over the 4 lanes of each quad
    dl0 += __shfl_xor_sync(~0u, dl0, 1);  dl1 += __shfl_xor_sync(~0u, dl1, 1);
    dl0 += __shfl_xor_sync(~0u, dl0, 2);  dl1 += __shfl_xor_sync(~0u, dl1, 2);
    if (c == 0) {
        dl0 += sdb;  dl1 += sdb;
        // stable softplus: sp(x) = max(x,0) + log(1 + exp(-|x|))
        float sp0 = fmaxf(dl0, 0.f) + __logf(1.f + __expf(-fabsf(dl0)));
        float sp1 = fmaxf(dl1, 0.f) + __logf(1.f + __expf(-fabsf(dl1)));
        ((float4*)out)[q] = make_float4(-sp0, dl0 - sp0, -sp1, dl1 - sp1);
    }
}

// ---------------- launch ----------------

template <typename... Args>
static void launch_pdl(void (*kern)(Args...), dim3 grid, dim3 block, Args... args) {
    cudaLaunchConfig_t cfg = {};
    cfg.gridDim = grid;
    cfg.blockDim = block;
    cfg.stream = 0;   // same (legacy default) stream as <<<>>> launches
    cudaLaunchAttribute attr[1];
    attr[0].id = cudaLaunchAttributeProgrammaticStreamSerialization;
    attr[0].val.programmaticStreamSerializationAllowed = 1;
    cfg.attrs = attr;
    cfg.numAttrs = 1;
    cudaLaunchKernelEx(&cfg, kern, args...);
}

extern "C" void kernel_launch(void* const* d_in, const int* in_sizes, int n_in,
                              void* d_out, int out_size) {
    const float* x    = (const float*)d_in[0];
    const int*   ei   = (const int*)  d_in[1];
    const float* w1l  = (const float*)d_in[2];
    const float* b1l  = (const float*)d_in[3];
    const float* w1r  = (const float*)d_in[4];
    const float* w2l  = (const float*)d_in[5];
    const float* b2l  = (const float*)d_in[6];
    const float* w2r  = (const float*)d_in[7];
    const float* fc1w = (const float*)d_in[8];
    const float* fc1b = (const float*)d_in[9];
    const float* fc2w = (const float*)d_in[10];
    const float* fc2b = (const float*)d_in[11];
    float* out = (float*)d_out;

    const int TB = 256;
    int gG  = (N_NODES + 127) / 128;          // 782, thread-per-node kernels
    int gE1 = (N_EDGES + TB - 1) / TB;        // 12500, quad-edge scatter
    int gE2 = (N_EDGES * 2 + TB - 1) / TB;    // 25000, dual-edge 4-lane edge kernel

    // A = x @ [w1_l|w1_r]  (normal launch: full order vs previous replay's k_edge)
    k_gemm_in<<<gG, 128>>>(x, w1l, w1r);
    // layer 1: scatter y -> agg (+cnt); fused combine+GEMM -> y|r (in place), zero agg
    launch_pdl(k_scatter, dim3(gE1), dim3(TB), ei, 1);
    launch_pdl(k_comb16, dim3(gG), dim3(128), w2l, w2r, b1l, (const float*)nullptr, 0, 0);
    // layer 2: scatter y -> agg; fused combine+GEMM with fc1 -> a|b, zero agg + cnt
    launch_pdl(k_scatter, dim3(gE1), dim3(TB), ei, 0);
    launch_pdl(k_comb16, dim3(gG), dim3(128), fc1w, fc1w, b2l, fc1b, 16, 1);
    // per-edge head + log_softmax (2 edges per quad)
    launch_pdl(k_edge, dim3(gE2), dim3(TB), ei, fc2w, fc2b, out);
}